// round 16
// baseline (speedup 1.0000x reference)
#include <cuda_runtime.h>
#include <cuda_fp16.h>
#include <cstdint>

// ===========================================================================
// CrossAttention round 16: single-fp16 mma.sync.
//  - attention: R13 straight-line body (the R14 pipeline was neutral)
//  - weight transpose rewritten with uint4 stores (was 6x under stream peak)
//  - gemm_qkv moved to ncu-profiled launch slot 3 (first profile since the
//    64x64-warp-tile rewrite)
// B=4, Sd=Se=2048, E=1024, H=16, d=64.
// ===========================================================================

#define EMBED 1024
#define HEADS 16
#define HDIM  64
#define BATCH 4
#define SEQ   2048
#define MTOT  (BATCH * SEQ)   // 8192

typedef __half  h16;
typedef __half2 h162;

// ---------------- scratch (device globals; allocation forbidden) -----------
__device__ h16 g_dec_h[MTOT * EMBED];
__device__ h16 g_enc_h[MTOT * EMBED];
__device__ h16 g_qh[MTOT * EMBED];
__device__ h16 g_kh[MTOT * EMBED];
__device__ h16 g_vh[MTOT * EMBED];
__device__ h16 g_oh[MTOT * EMBED];
__device__ h16 g_wq [EMBED * EMBED];
__device__ h16 g_wkv[2 * EMBED * EMBED];   // rows 0..1023 Wk^T, 1024..2047 Wv^T
__device__ h16 g_wo [EMBED * EMBED];

// ---------------- low-level helpers ----------------------------------------
__device__ __forceinline__ uint32_t smem_u32(const void* p) {
    uint32_t a;
    asm("{ .reg .u64 t; cvta.to.shared.u64 t, %1; cvt.u32.u64 %0, t; }"
        : "=r"(a) : "l"(p));
    return a;
}
__device__ __forceinline__ uint32_t swz128(uint32_t off) {
    return off ^ ((off >> 3) & 0x70);
}
__device__ __forceinline__ void cpa16(uint32_t saddr, const void* g) {
    asm volatile("cp.async.cg.shared.global [%0], [%1], 16;"
                 :: "r"(saddr), "l"(g) : "memory");
}
#define CP_COMMIT() asm volatile("cp.async.commit_group;" ::: "memory")
#define CP_WAIT(n)  asm volatile("cp.async.wait_group %0;" :: "n"(n) : "memory")

__device__ __forceinline__ void ldmx4(uint32_t* r, uint32_t addr) {
    asm volatile("ldmatrix.sync.aligned.m8n8.x4.shared.b16 {%0,%1,%2,%3}, [%4];"
                 : "=r"(r[0]), "=r"(r[1]), "=r"(r[2]), "=r"(r[3]) : "r"(addr));
}
__device__ __forceinline__ void ldmx4t(uint32_t* r, uint32_t addr) {
    asm volatile("ldmatrix.sync.aligned.m8n8.x4.trans.shared.b16 {%0,%1,%2,%3}, [%4];"
                 : "=r"(r[0]), "=r"(r[1]), "=r"(r[2]), "=r"(r[3]) : "r"(addr));
}
__device__ __forceinline__ void mma16816(float* d, const uint32_t* a,
                                         const uint32_t* b) {
    asm volatile(
        "mma.sync.aligned.m16n8k16.row.col.f32.f16.f16.f32 "
        "{%0,%1,%2,%3}, {%4,%5,%6,%7}, {%8,%9}, {%0,%1,%2,%3};"
        : "+f"(d[0]), "+f"(d[1]), "+f"(d[2]), "+f"(d[3])
        : "r"(a[0]), "r"(a[1]), "r"(a[2]), "r"(a[3]), "r"(b[0]), "r"(b[1]));
}
__device__ __forceinline__ uint32_t packf2(float a, float b) {
    h162 t = __floats2half2_rn(a, b);
    return *(uint32_t*)&t;
}
__device__ __forceinline__ float ex2(float x) {
    float r;
    asm("ex2.approx.ftz.f32 %0, %1;" : "=f"(r) : "f"(x));
    return r;
}

// ---------------------------------------------------------------------------
// fused fp32->fp16 for dec and enc: 8 elems/thread, uint4 stores
// ---------------------------------------------------------------------------
__global__ __launch_bounds__(256)
void tofp16_2(const float* __restrict__ dec, const float* __restrict__ enc,
              h16* __restrict__ dh, h16* __restrict__ eh, int n8)
{
    int i = blockIdx.x * 256 + threadIdx.x;
    const float* in; h16* out; int j;
    if (i < n8) { in = dec; out = dh; j = i; }
    else        { in = enc; out = eh; j = i - n8; }
    float4 a = ((const float4*)in)[j * 2];
    float4 b = ((const float4*)in)[j * 2 + 1];
    uint4 o;
    o.x = packf2(a.x, a.y); o.y = packf2(a.z, a.w);
    o.z = packf2(b.x, b.y); o.w = packf2(b.z, b.w);
    ((uint4*)out)[j] = o;
}

// ---------------------------------------------------------------------------
// weight transpose, wide stores: W[K][N] fp32 -> T[N][K] fp16.
// Tile: 32 k-rows x 64 n-cols, 256 threads.  Each thread stores one uint4
// (8 contiguous fp16 k-values) -> fully coalesced 16B stores.
// blockIdx.z selects which of up to 3 weights this launch handles.
// ---------------------------------------------------------------------------
__global__ __launch_bounds__(256)
void wtransx(const float* __restrict__ W0, const float* __restrict__ W1,
             const float* __restrict__ W2, h16* __restrict__ T0,
             h16* __restrict__ T1, h16* __restrict__ T2)
{
    __shared__ float t[32][65];
    const int k0 = blockIdx.x * 32, n0 = blockIdx.y * 64;
    const int tx = threadIdx.x, ty = threadIdx.y;   // (32, 8)
    const int z = blockIdx.z;
    const float* W = (z == 0) ? W0 : (z == 1) ? W1 : W2;
    h16* T = (z == 0) ? T0 : (z == 1) ? T1 : T2;

    // load 32 k-rows x 64 n-cols (two 32-wide column groups)
#pragma unroll
    for (int j = 0; j < 4; ++j) {
        int k = ty + j * 8;
        t[k][tx]      = W[(size_t)(k0 + k) * EMBED + n0 + tx];
        t[k][tx + 32] = W[(size_t)(k0 + k) * EMBED + n0 + tx + 32];
    }
    __syncthreads();

    // store: thread -> (n, 8-k group); one uint4 per thread
    const int tid = ty * 32 + tx;
    const int n  = tid >> 2;          // 0..63
    const int kq = (tid & 3) * 8;     // 0,8,16,24
    uint4 o;
    o.x = packf2(t[kq + 0][n], t[kq + 1][n]);
    o.y = packf2(t[kq + 2][n], t[kq + 3][n]);
    o.z = packf2(t[kq + 4][n], t[kq + 5][n]);
    o.w = packf2(t[kq + 6][n], t[kq + 7][n]);
    *(uint4*)(T + (size_t)(n0 + n) * EMBED + k0 + kq) = o;
}

// ---------------------------------------------------------------------------
// GEMM core: 128x128 tile, BK=64, 4 warps (64x64 each), 3-stage cp.async,
// 128-thread blocks, 2 blocks/SM.
// ---------------------------------------------------------------------------
#define GTILE 16384            // 128 rows x 128B
#define GSTG  (2 * GTILE)      // A, B
#define GSMEM (3 * GSTG + 1024)

struct GemmAcc { float a[4][8][4]; };

__device__ __forceinline__ void gemm_core(const h16* pA, const h16* pB, int K,
                                          uint32_t tiles, int tid, int lane,
                                          int wm, int wn, GemmAcc& acc)
{
    const int NC = K / 64;
    auto load_stage = [&](int c, int s) {
        const uint32_t tb = tiles + s * GSTG;
        const int kc = c * 64;
#pragma unroll
        for (int i = 0; i < 8; ++i) {
            int idx = tid + i * 128;
            int r = idx >> 3, c16 = idx & 7;
            uint32_t soff = swz128((uint32_t)(r * 128 + c16 * 16));
            size_t go = (size_t)r * K + kc + c16 * 8;
            cpa16(tb + 0 * GTILE + soff, pA + go);
            cpa16(tb + 1 * GTILE + soff, pB + go);
        }
        CP_COMMIT();
    };

#pragma unroll
    for (int mt = 0; mt < 4; ++mt)
#pragma unroll
        for (int nt = 0; nt < 8; ++nt)
#pragma unroll
            for (int j = 0; j < 4; ++j) acc.a[mt][nt][j] = 0.f;

    load_stage(0, 0);
    load_stage(1, 1);

    int s = 0;
    for (int c = 0; c < NC; ++c) {
        if (c + 1 < NC) { CP_WAIT(1); } else { CP_WAIT(0); }
        __syncthreads();
        if (c + 2 < NC) {
            int s2 = s + 2; if (s2 >= 3) s2 -= 3;
            load_stage(c + 2, s2);
        }
        const uint32_t tb = tiles + s * GSTG;
#pragma unroll
        for (int ks = 0; ks < 4; ++ks) {
            uint32_t ah[4][4], bb[4][4];
#pragma unroll
            for (int mt = 0; mt < 4; ++mt) {
                uint32_t r  = wm + mt * 16 + (lane & 15);
                uint32_t ck = ks * 2 + (lane >> 4);
                uint32_t off = swz128(r * 128 + ck * 16);
                ldmx4(ah[mt], tb + 0 * GTILE + off);
            }
#pragma unroll
            for (int np = 0; np < 4; ++np) {
                uint32_t r  = wn + (np * 2 + (lane >> 4)) * 8 + (lane & 7);
                uint32_t ck = ks * 2 + ((lane >> 3) & 1);
                uint32_t off = swz128(r * 128 + ck * 16);
                ldmx4(bb[np], tb + 1 * GTILE + off);
            }
#pragma unroll
            for (int mt = 0; mt < 4; ++mt)
#pragma unroll
                for (int nt = 0; nt < 8; ++nt)
                    mma16816(acc.a[mt][nt], ah[mt], &bb[nt >> 1][(nt & 1) * 2]);
        }
        if (++s == 3) s = 0;
    }
    __syncthreads();
}

// ---------------------------------------------------------------------------
// Fused Q+K+V projection.  grid = (24, 64), 128 threads (4 warps 2x2).
// ---------------------------------------------------------------------------
__global__ __launch_bounds__(128, 2)
void gemm_qkv(const h16* __restrict__ dh, const h16* __restrict__ eh,
              const h16* __restrict__ wq, const h16* __restrict__ wkv,
              h16* __restrict__ qh, h16* __restrict__ kh,
              h16* __restrict__ vh)
{
    extern __shared__ char raw[];
    const uint32_t tiles = (smem_u32(raw) + 1023) & ~1023u;
    const int tid = threadIdx.x, lane = tid & 31, wid = tid >> 5;
    const int wm = (wid & 1) * 64, wn = (wid >> 1) * 64;
    const int row0 = blockIdx.y * 128;
    const int bx = blockIdx.x;

    const h16 *A, *B; h16* C; int col0;
    if (bx < 8) {
        A = dh;  B = wq  + (size_t)bx * 128 * EMBED;  C = qh;  col0 = bx * 128;
    } else {
        int x = bx - 8;
        A = eh;  B = wkv + (size_t)x * 128 * EMBED;
        int gc = x * 128;
        if (gc < EMBED) { C = kh; col0 = gc; }
        else            { C = vh; col0 = gc - EMBED; }
    }

    GemmAcc acc;
    gemm_core(A + (size_t)row0 * EMBED, B, EMBED, tiles, tid, lane, wm, wn, acc);

#pragma unroll
    for (int mt = 0; mt < 4; ++mt)
#pragma unroll
        for (int nt = 0; nt < 8; ++nt) {
            int r0 = row0 + wm + mt * 16 + (lane >> 2);
            int cc = col0 + wn + nt * 8 + (lane & 3) * 2;
            *(uint32_t*)(C + (size_t)r0 * EMBED + cc) =
                packf2(acc.a[mt][nt][0], acc.a[mt][nt][1]);
            *(uint32_t*)(C + (size_t)(r0 + 8) * EMBED + cc) =
                packf2(acc.a[mt][nt][2], acc.a[mt][nt][3]);
        }
}

// ---------------------------------------------------------------------------
// Output projection: fp32 + bias.  grid = (8, 64), 128 threads.
// ---------------------------------------------------------------------------
__global__ __launch_bounds__(128, 2)
void gemm_o(const h16* __restrict__ oh, const h16* __restrict__ wo,
            const float* __restrict__ bias, float* __restrict__ out)
{
    extern __shared__ char raw[];
    const uint32_t tiles = (smem_u32(raw) + 1023) & ~1023u;
    const int tid = threadIdx.x, lane = tid & 31, wid = tid >> 5;
    const int wm = (wid & 1) * 64, wn = (wid >> 1) * 64;
    const int row0 = blockIdx.y * 128, col0 = blockIdx.x * 128;

    GemmAcc acc;
    gemm_core(oh + (size_t)row0 * EMBED, wo + (size_t)col0 * EMBED, EMBED,
              tiles, tid, lane, wm, wn, acc);

#pragma unroll
    for (int mt = 0; mt < 4; ++mt)
#pragma unroll
        for (int nt = 0; nt < 8; ++nt) {
            int r0 = row0 + wm + mt * 16 + (lane >> 2);
            int cc = col0 + wn + nt * 8 + (lane & 3) * 2;
            float b0 = bias[cc], b1 = bias[cc + 1];
            *(float2*)(out + (size_t)r0 * EMBED + cc) =
                make_float2(acc.a[mt][nt][0] + b0, acc.a[mt][nt][1] + b1);
            *(float2*)(out + (size_t)(r0 + 8) * EMBED + cc) =
                make_float2(acc.a[mt][nt][2] + b0, acc.a[mt][nt][3] + b1);
        }
}

// ---------------------------------------------------------------------------
// Flash attention (R13 straight-line body): 4 warps x 32 q-rows, KV chunk 64,
// 2 blocks/SM.  Max-free exp; per-thread l partials; end-of-kernel reduce.
// ---------------------------------------------------------------------------
#define AQH   0
#define AST   16384            // stage s at AST + s*ASTG
#define ASTG  16384            // K 8KB + V 8KB
#define ASMEM (AST + 2 * ASTG + 1024)

__global__ __launch_bounds__(128, 2)
void attn_mma(const h16* __restrict__ Qh, const h16* __restrict__ Kh,
              const h16* __restrict__ Vh, h16* __restrict__ Oh)
{
    extern __shared__ char raw[];
    const uint32_t ab = (smem_u32(raw) + 1023) & ~1023u;

    const int tid = threadIdx.x, lane = tid & 31, wid = tid >> 5;
    const int wq = wid * 32;

    const int q0 = blockIdx.x * 128;
    const int bh = blockIdx.y;
    const int b  = bh / HEADS, h = bh - b * HEADS;
    const size_t gbase = (size_t)b * SEQ * EMBED + (size_t)h * HDIM;

    // Q load (once): 128 rows x 128B
#pragma unroll
    for (int i = 0; i < 8; ++i) {
        int idx = tid + i * 128;
        int r = idx >> 3, c16 = idx & 7;
        uint32_t soff = swz128((uint32_t)(r * 128 + c16 * 16));
        size_t go = gbase + (size_t)(q0 + r) * EMBED + c16 * 8;
        cpa16(ab + AQH + soff, Qh + go);
    }
    CP_COMMIT();

    auto kvload = [&](int c, int s) {
        const uint32_t tb = ab + AST + s * ASTG;
#pragma unroll
        for (int i = 0; i < 4; ++i) {
            int idx = tid + i * 128;          // 0..511
            int r = idx >> 3, c16 = idx & 7;  // r < 64
            uint32_t soff = swz128((uint32_t)(r * 128 + c16 * 16));
            size_t go = gbase + (size_t)(c * 64 + r) * EMBED + c16 * 8;
            cpa16(tb +    0 + soff, Kh + go);
            cpa16(tb + 8192 + soff, Vh + go);
        }
        CP_COMMIT();
    };

    kvload(0, 0);
    CP_WAIT(0);
    __syncthreads();

    // Q fragments -> registers (persist): 2 m-blocks x 4 k-slices
    uint32_t qf[2][4][4];
#pragma unroll
    for (int mb = 0; mb < 2; ++mb)
#pragma unroll
        for (int ks = 0; ks < 4; ++ks) {
            uint32_t r  = wq + mb * 16 + (lane & 15);
            uint32_t ck = ks * 2 + (lane >> 4);
            uint32_t off = swz128(r * 128 + ck * 16);
            ldmx4(qf[mb][ks], ab + AQH + off);
        }

    const float CSC = 0.18033688011f;   // log2(e) / 8
    float lp[4] = {0.f, 0.f, 0.f, 0.f}; // per-thread row-sum partials
    float oac[2][8][4];
#pragma unroll
    for (int mb = 0; mb < 2; ++mb)
#pragma unroll
        for (int nt = 0; nt < 8; ++nt)
#pragma unroll
            for (int j = 0; j < 4; ++j) oac[mb][nt][j] = 0.f;

    const int NKV = SEQ / 64;   // 32
    for (int c = 0; c < NKV; ++c) {
        const int s = c & 1;
        const uint32_t tb = ab + AST + s * ASTG;
        if (c + 1 < NKV) kvload(c + 1, s ^ 1);

        // ---- S = Q K^T  (32 q-rows x 64 kv-cols per warp) ----
        float z[2][8][4];
#pragma unroll
        for (int mb = 0; mb < 2; ++mb)
#pragma unroll
            for (int nt = 0; nt < 8; ++nt)
#pragma unroll
                for (int j = 0; j < 4; ++j) z[mb][nt][j] = 0.f;

#pragma unroll
        for (int ks = 0; ks < 4; ++ks) {
            uint32_t k4[4][4];
#pragma unroll
            for (int np = 0; np < 4; ++np) {
                uint32_t r  = (np * 2 + (lane >> 4)) * 8 + (lane & 7);
                uint32_t ck = ks * 2 + ((lane >> 3) & 1);
                uint32_t off = swz128(r * 128 + ck * 16);
                ldmx4(k4[np], tb + off);
            }
#pragma unroll
            for (int mb = 0; mb < 2; ++mb)
#pragma unroll
                for (int nt = 0; nt < 8; ++nt)
                    mma16816(z[mb][nt], qf[mb][ks], &k4[nt >> 1][(nt & 1) * 2]);
        }

        // ---- elementwise exp + pack P to fp16; accumulate l partials ----
        uint32_t pp[2][16];
#pragma unroll
        for (int mb = 0; mb < 2; ++mb) {
            float s0 = 0.f, s1 = 0.f;
#pragma unroll
            for (int nt = 0; nt < 8; ++nt) {
                float e0 = ex2(z[mb][nt][0] * CSC);
                float e1 = ex2(z[mb][nt][1] * CSC);
                float e2 = ex2(z[mb][nt][2] * CSC);
                float e3 = ex2(z[mb][nt][3] * CSC);
                s0 += e0 + e1;
                s1 += e2 + e3;
                pp[mb][nt * 2]     = packf2(e0, e1);
                pp[mb][nt * 2 + 1] = packf2(e2, e3);
            }
            lp[2 * mb]     += s0;
            lp[2 * mb + 1] += s1;
        }

        // ---- O += P V  (V frags shared across m-blocks) ----
#pragma unroll
        for (int ksv = 0; ksv < 4; ++ksv) {
            uint32_t v4[4][4];
#pragma unroll
            for (int np = 0; np < 4; ++np) {
                uint32_t r  = ksv * 16 + ((lane >> 3) & 1) * 8 + (lane & 7);
                uint32_t ck = np * 2 + (lane >> 4);
                uint32_t off = swz128(r * 128 + ck * 16);
                ldmx4t(v4[np], tb + 8192 + off);
            }
#pragma unroll
            for (int mb = 0; mb < 2; ++mb) {
                const uint32_t* pa = &pp[mb][ksv * 4];
#pragma unroll
                for (int nt = 0; nt < 8; ++nt)
                    mma16816(oac[mb][nt], pa, &v4[nt >> 1][(nt & 1) * 2]);
            }
        }

        CP_WAIT(0);
        __syncthreads();
    }

    // ---- reduce l over the quad (cols spread across 4 lanes) ----
#pragma unroll
    for (int g = 0; g < 4; ++g) {
        lp[g] += __shfl_xor_sync(0xffffffffu, lp[g], 1);
        lp[g] += __shfl_xor_sync(0xffffffffu, lp[g], 2);
    }

    // ---- normalize + write Oh ----
#pragma unroll
    for (int mb = 0; mb < 2; ++mb) {
        float i0 = 1.0f / lp[2 * mb], i1 = 1.0f / lp[2 * mb + 1];
        int gr0 = q0 + wq + mb * 16 + (lane >> 2);
#pragma unroll
        for (int nt = 0; nt < 8; ++nt) {
            int cc = nt * 8 + (lane & 3) * 2;
            size_t o0 = gbase + (size_t)gr0 * EMBED + cc;
            size_t o1 = o0 + (size_t)8 * EMBED;
            *(uint32_t*)(Oh + o0) = packf2(oac[mb][nt][0] * i0,
                                           oac[mb][nt][1] * i0);
            *(uint32_t*)(Oh + o1) = packf2(oac[mb][nt][2] * i1,
                                           oac[mb][nt][3] * i1);
        }
    }
}

// ---------------------------------------------------------------------------
// Launch: 6 kernels.  gemm_qkv at launch index 3 (the ncu-profiled slot).
// ---------------------------------------------------------------------------
extern "C" void kernel_launch(void* const* d_in, const int* in_sizes, int n_in,
                              void* d_out, int out_size)
{
    const float* dec = (const float*)d_in[0];
    const float* enc = (const float*)d_in[1];
    const float* Wq  = (const float*)d_in[2];
    const float* Wk  = (const float*)d_in[3];
    const float* Wv  = (const float*)d_in[4];
    const float* Wo  = (const float*)d_in[5];
    const float* bo  = (const float*)d_in[6];
    float* out = (float*)d_out;

    h16 *dh, *eh, *qh, *kh, *vh, *oh, *wq, *wkv, *wo;
    cudaGetSymbolAddress((void**)&dh, g_dec_h);
    cudaGetSymbolAddress((void**)&eh, g_enc_h);
    cudaGetSymbolAddress((void**)&qh, g_qh);
    cudaGetSymbolAddress((void**)&kh, g_kh);
    cudaGetSymbolAddress((void**)&vh, g_vh);
    cudaGetSymbolAddress((void**)&oh, g_oh);
    cudaGetSymbolAddress((void**)&wq, g_wq);
    cudaGetSymbolAddress((void**)&wkv, g_wkv);
    cudaGetSymbolAddress((void**)&wo, g_wo);

    cudaFuncSetAttribute(gemm_qkv,
                         cudaFuncAttributeMaxDynamicSharedMemorySize, GSMEM);
    cudaFuncSetAttribute(gemm_o,
                         cudaFuncAttributeMaxDynamicSharedMemorySize, GSMEM);
    cudaFuncSetAttribute(attn_mma,
                         cudaFuncAttributeMaxDynamicSharedMemorySize, ASMEM);

    const int n8 = MTOT * EMBED / 8;   // 1,048,576

    // 0: Wq, Wk, Wv transposes (wide stores)
    wtransx<<<dim3(EMBED / 32, EMBED / 64, 3), dim3(32, 8)>>>(
        Wq, Wk, Wv, wq, wkv, wkv + (size_t)EMBED * EMBED);
    // 1: Wo transpose
    wtransx<<<dim3(EMBED / 32, EMBED / 64, 1), dim3(32, 8)>>>(
        Wo, Wo, Wo, wo, wo, wo);
    // 2: dec + enc fp16 conversion
    tofp16_2<<<2 * n8 / 256, 256>>>(dec, enc, dh, eh, n8);
    // 3: fused Q+K+V projection  (profiled slot)
    gemm_qkv<<<dim3(24, MTOT / 128), 128, GSMEM>>>(dh, eh, wq, wkv,
                                                   qh, kh, vh);
    // 4: attention
    attn_mma<<<dim3(SEQ / 128, BATCH * HEADS), 128, ASMEM>>>(qh, kh, vh, oh);
    // 5: output projection + bias
    gemm_o<<<dim3(8, MTOT / 128), 128, GSMEM>>>(oh, wo, bo, out);
}

// round 17
// speedup vs baseline: 1.0101x; 1.0101x over previous
#include <cuda_runtime.h>
#include <cuda_fp16.h>
#include <cstdint>

// ===========================================================================
// CrossAttention round 17 (consolidation): R13 best config + single-launch
// wide-store weight transpose (grid.z=4).  Single-fp16 mma.sync throughout;
// max-free softmax; per-thread l partials.
// B=4, Sd=Se=2048, E=1024, H=16, d=64.
// ===========================================================================

#define EMBED 1024
#define HEADS 16
#define HDIM  64
#define BATCH 4
#define SEQ   2048
#define MTOT  (BATCH * SEQ)   // 8192

typedef __half  h16;
typedef __half2 h162;

// ---------------- scratch (device globals; allocation forbidden) -----------
__device__ h16 g_dec_h[MTOT * EMBED];
__device__ h16 g_enc_h[MTOT * EMBED];
__device__ h16 g_qh[MTOT * EMBED];
__device__ h16 g_kh[MTOT * EMBED];
__device__ h16 g_vh[MTOT * EMBED];
__device__ h16 g_oh[MTOT * EMBED];
__device__ h16 g_wq [EMBED * EMBED];
__device__ h16 g_wkv[2 * EMBED * EMBED];   // rows 0..1023 Wk^T, 1024..2047 Wv^T
__device__ h16 g_wo [EMBED * EMBED];

// ---------------- low-level helpers ----------------------------------------
__device__ __forceinline__ uint32_t smem_u32(const void* p) {
    uint32_t a;
    asm("{ .reg .u64 t; cvta.to.shared.u64 t, %1; cvt.u32.u64 %0, t; }"
        : "=r"(a) : "l"(p));
    return a;
}
__device__ __forceinline__ uint32_t swz128(uint32_t off) {
    return off ^ ((off >> 3) & 0x70);
}
__device__ __forceinline__ void cpa16(uint32_t saddr, const void* g) {
    asm volatile("cp.async.cg.shared.global [%0], [%1], 16;"
                 :: "r"(saddr), "l"(g) : "memory");
}
#define CP_COMMIT() asm volatile("cp.async.commit_group;" ::: "memory")
#define CP_WAIT(n)  asm volatile("cp.async.wait_group %0;" :: "n"(n) : "memory")

__device__ __forceinline__ void ldmx4(uint32_t* r, uint32_t addr) {
    asm volatile("ldmatrix.sync.aligned.m8n8.x4.shared.b16 {%0,%1,%2,%3}, [%4];"
                 : "=r"(r[0]), "=r"(r[1]), "=r"(r[2]), "=r"(r[3]) : "r"(addr));
}
__device__ __forceinline__ void ldmx4t(uint32_t* r, uint32_t addr) {
    asm volatile("ldmatrix.sync.aligned.m8n8.x4.trans.shared.b16 {%0,%1,%2,%3}, [%4];"
                 : "=r"(r[0]), "=r"(r[1]), "=r"(r[2]), "=r"(r[3]) : "r"(addr));
}
__device__ __forceinline__ void mma16816(float* d, const uint32_t* a,
                                         const uint32_t* b) {
    asm volatile(
        "mma.sync.aligned.m16n8k16.row.col.f32.f16.f16.f32 "
        "{%0,%1,%2,%3}, {%4,%5,%6,%7}, {%8,%9}, {%0,%1,%2,%3};"
        : "+f"(d[0]), "+f"(d[1]), "+f"(d[2]), "+f"(d[3])
        : "r"(a[0]), "r"(a[1]), "r"(a[2]), "r"(a[3]), "r"(b[0]), "r"(b[1]));
}
__device__ __forceinline__ uint32_t packf2(float a, float b) {
    h162 t = __floats2half2_rn(a, b);
    return *(uint32_t*)&t;
}
__device__ __forceinline__ float ex2(float x) {
    float r;
    asm("ex2.approx.ftz.f32 %0, %1;" : "=f"(r) : "f"(x));
    return r;
}

// ---------------------------------------------------------------------------
// fused fp32->fp16 for dec and enc: 8 elems/thread, uint4 stores
// ---------------------------------------------------------------------------
__global__ __launch_bounds__(256)
void tofp16_2(const float* __restrict__ dec, const float* __restrict__ enc,
              h16* __restrict__ dh, h16* __restrict__ eh, int n8)
{
    int i = blockIdx.x * 256 + threadIdx.x;
    const float* in; h16* out; int j;
    if (i < n8) { in = dec; out = dh; j = i; }
    else        { in = enc; out = eh; j = i - n8; }
    float4 a = ((const float4*)in)[j * 2];
    float4 b = ((const float4*)in)[j * 2 + 1];
    uint4 o;
    o.x = packf2(a.x, a.y); o.y = packf2(a.z, a.w);
    o.z = packf2(b.x, b.y); o.w = packf2(b.z, b.w);
    ((uint4*)out)[j] = o;
}

// ---------------------------------------------------------------------------
// weight transpose, wide stores, ALL 4 weights in one launch (grid.z=4):
// W[K][N] fp32 -> T[N][K] fp16.  Tile 32k x 64n, 256 threads; each thread
// stores one uint4 (8 contiguous fp16 k-values).
// ---------------------------------------------------------------------------
__global__ __launch_bounds__(256)
void wtransx(const float* __restrict__ Wq, const float* __restrict__ Wk,
             const float* __restrict__ Wv, const float* __restrict__ Wo,
             h16* __restrict__ Tq, h16* __restrict__ Tkv,
             h16* __restrict__ To)
{
    __shared__ float t[32][65];
    const int k0 = blockIdx.x * 32, n0 = blockIdx.y * 64;
    const int tx = threadIdx.x, ty = threadIdx.y;   // (32, 8)
    const int z = blockIdx.z;
    const float* W = (z == 0) ? Wq : (z == 1) ? Wk : (z == 2) ? Wv : Wo;
    h16* T = (z == 0) ? Tq : (z == 1) ? Tkv
           : (z == 2) ? (Tkv + (size_t)EMBED * EMBED) : To;

#pragma unroll
    for (int j = 0; j < 4; ++j) {
        int k = ty + j * 8;
        t[k][tx]      = W[(size_t)(k0 + k) * EMBED + n0 + tx];
        t[k][tx + 32] = W[(size_t)(k0 + k) * EMBED + n0 + tx + 32];
    }
    __syncthreads();

    const int tid = ty * 32 + tx;
    const int n  = tid >> 2;          // 0..63
    const int kq = (tid & 3) * 8;     // 0,8,16,24
    uint4 o;
    o.x = packf2(t[kq + 0][n], t[kq + 1][n]);
    o.y = packf2(t[kq + 2][n], t[kq + 3][n]);
    o.z = packf2(t[kq + 4][n], t[kq + 5][n]);
    o.w = packf2(t[kq + 6][n], t[kq + 7][n]);
    *(uint4*)(T + (size_t)(n0 + n) * EMBED + k0 + kq) = o;
}

// ---------------------------------------------------------------------------
// GEMM core: 128x128 tile, BK=64, 4 warps (64x64 each), 3-stage cp.async,
// 128-thread blocks, 2 blocks/SM.
// ---------------------------------------------------------------------------
#define GTILE 16384            // 128 rows x 128B
#define GSTG  (2 * GTILE)      // A, B
#define GSMEM (3 * GSTG + 1024)

struct GemmAcc { float a[4][8][4]; };

__device__ __forceinline__ void gemm_core(const h16* pA, const h16* pB, int K,
                                          uint32_t tiles, int tid, int lane,
                                          int wm, int wn, GemmAcc& acc)
{
    const int NC = K / 64;
    auto load_stage = [&](int c, int s) {
        const uint32_t tb = tiles + s * GSTG;
        const int kc = c * 64;
#pragma unroll
        for (int i = 0; i < 8; ++i) {
            int idx = tid + i * 128;
            int r = idx >> 3, c16 = idx & 7;
            uint32_t soff = swz128((uint32_t)(r * 128 + c16 * 16));
            size_t go = (size_t)r * K + kc + c16 * 8;
            cpa16(tb + 0 * GTILE + soff, pA + go);
            cpa16(tb + 1 * GTILE + soff, pB + go);
        }
        CP_COMMIT();
    };

#pragma unroll
    for (int mt = 0; mt < 4; ++mt)
#pragma unroll
        for (int nt = 0; nt < 8; ++nt)
#pragma unroll
            for (int j = 0; j < 4; ++j) acc.a[mt][nt][j] = 0.f;

    load_stage(0, 0);
    load_stage(1, 1);

    int s = 0;
    for (int c = 0; c < NC; ++c) {
        if (c + 1 < NC) { CP_WAIT(1); } else { CP_WAIT(0); }
        __syncthreads();
        if (c + 2 < NC) {
            int s2 = s + 2; if (s2 >= 3) s2 -= 3;
            load_stage(c + 2, s2);
        }
        const uint32_t tb = tiles + s * GSTG;
#pragma unroll
        for (int ks = 0; ks < 4; ++ks) {
            uint32_t ah[4][4], bb[4][4];
#pragma unroll
            for (int mt = 0; mt < 4; ++mt) {
                uint32_t r  = wm + mt * 16 + (lane & 15);
                uint32_t ck = ks * 2 + (lane >> 4);
                uint32_t off = swz128(r * 128 + ck * 16);
                ldmx4(ah[mt], tb + 0 * GTILE + off);
            }
#pragma unroll
            for (int np = 0; np < 4; ++np) {
                uint32_t r  = wn + (np * 2 + (lane >> 4)) * 8 + (lane & 7);
                uint32_t ck = ks * 2 + ((lane >> 3) & 1);
                uint32_t off = swz128(r * 128 + ck * 16);
                ldmx4(bb[np], tb + 1 * GTILE + off);
            }
#pragma unroll
            for (int mt = 0; mt < 4; ++mt)
#pragma unroll
                for (int nt = 0; nt < 8; ++nt)
                    mma16816(acc.a[mt][nt], ah[mt], &bb[nt >> 1][(nt & 1) * 2]);
        }
        if (++s == 3) s = 0;
    }
    __syncthreads();
}

// ---------------------------------------------------------------------------
// Fused Q+K+V projection.  grid = (24, 64), 128 threads (4 warps 2x2).
// ---------------------------------------------------------------------------
__global__ __launch_bounds__(128, 2)
void gemm_qkv(const h16* __restrict__ dh, const h16* __restrict__ eh,
              const h16* __restrict__ wq, const h16* __restrict__ wkv,
              h16* __restrict__ qh, h16* __restrict__ kh,
              h16* __restrict__ vh)
{
    extern __shared__ char raw[];
    const uint32_t tiles = (smem_u32(raw) + 1023) & ~1023u;
    const int tid = threadIdx.x, lane = tid & 31, wid = tid >> 5;
    const int wm = (wid & 1) * 64, wn = (wid >> 1) * 64;
    const int row0 = blockIdx.y * 128;
    const int bx = blockIdx.x;

    const h16 *A, *B; h16* C; int col0;
    if (bx < 8) {
        A = dh;  B = wq  + (size_t)bx * 128 * EMBED;  C = qh;  col0 = bx * 128;
    } else {
        int x = bx - 8;
        A = eh;  B = wkv + (size_t)x * 128 * EMBED;
        int gc = x * 128;
        if (gc < EMBED) { C = kh; col0 = gc; }
        else            { C = vh; col0 = gc - EMBED; }
    }

    GemmAcc acc;
    gemm_core(A + (size_t)row0 * EMBED, B, EMBED, tiles, tid, lane, wm, wn, acc);

#pragma unroll
    for (int mt = 0; mt < 4; ++mt)
#pragma unroll
        for (int nt = 0; nt < 8; ++nt) {
            int r0 = row0 + wm + mt * 16 + (lane >> 2);
            int cc = col0 + wn + nt * 8 + (lane & 3) * 2;
            *(uint32_t*)(C + (size_t)r0 * EMBED + cc) =
                packf2(acc.a[mt][nt][0], acc.a[mt][nt][1]);
            *(uint32_t*)(C + (size_t)(r0 + 8) * EMBED + cc) =
                packf2(acc.a[mt][nt][2], acc.a[mt][nt][3]);
        }
}

// ---------------------------------------------------------------------------
// Output projection: fp32 + bias.  grid = (8, 64), 128 threads.
// ---------------------------------------------------------------------------
__global__ __launch_bounds__(128, 2)
void gemm_o(const h16* __restrict__ oh, const h16* __restrict__ wo,
            const float* __restrict__ bias, float* __restrict__ out)
{
    extern __shared__ char raw[];
    const uint32_t tiles = (smem_u32(raw) + 1023) & ~1023u;
    const int tid = threadIdx.x, lane = tid & 31, wid = tid >> 5;
    const int wm = (wid & 1) * 64, wn = (wid >> 1) * 64;
    const int row0 = blockIdx.y * 128, col0 = blockIdx.x * 128;

    GemmAcc acc;
    gemm_core(oh + (size_t)row0 * EMBED, wo + (size_t)col0 * EMBED, EMBED,
              tiles, tid, lane, wm, wn, acc);

#pragma unroll
    for (int mt = 0; mt < 4; ++mt)
#pragma unroll
        for (int nt = 0; nt < 8; ++nt) {
            int r0 = row0 + wm + mt * 16 + (lane >> 2);
            int cc = col0 + wn + nt * 8 + (lane & 3) * 2;
            float b0 = bias[cc], b1 = bias[cc + 1];
            *(float2*)(out + (size_t)r0 * EMBED + cc) =
                make_float2(acc.a[mt][nt][0] + b0, acc.a[mt][nt][1] + b1);
            *(float2*)(out + (size_t)(r0 + 8) * EMBED + cc) =
                make_float2(acc.a[mt][nt][2] + b0, acc.a[mt][nt][3] + b1);
        }
}

// ---------------------------------------------------------------------------
// Flash attention (R13 body): 4 warps x 32 q-rows, KV chunk 64, 2 blocks/SM.
// Max-free exp; per-thread l partials; end-of-kernel quad reduce.
// ---------------------------------------------------------------------------
#define AQH   0
#define AST   16384            // stage s at AST + s*ASTG
#define ASTG  16384            // K 8KB + V 8KB
#define ASMEM (AST + 2 * ASTG + 1024)

__global__ __launch_bounds__(128, 2)
void attn_mma(const h16* __restrict__ Qh, const h16* __restrict__ Kh,
              const h16* __restrict__ Vh, h16* __restrict__ Oh)
{
    extern __shared__ char raw[];
    const uint32_t ab = (smem_u32(raw) + 1023) & ~1023u;

    const int tid = threadIdx.x, lane = tid & 31, wid = tid >> 5;
    const int wq = wid * 32;

    const int q0 = blockIdx.x * 128;
    const int bh = blockIdx.y;
    const int b  = bh / HEADS, h = bh - b * HEADS;
    const size_t gbase = (size_t)b * SEQ * EMBED + (size_t)h * HDIM;

    // Q load (once): 128 rows x 128B
#pragma unroll
    for (int i = 0; i < 8; ++i) {
        int idx = tid + i * 128;
        int r = idx >> 3, c16 = idx & 7;
        uint32_t soff = swz128((uint32_t)(r * 128 + c16 * 16));
        size_t go = gbase + (size_t)(q0 + r) * EMBED + c16 * 8;
        cpa16(ab + AQH + soff, Qh + go);
    }
    CP_COMMIT();

    auto kvload = [&](int c, int s) {
        const uint32_t tb = ab + AST + s * ASTG;
#pragma unroll
        for (int i = 0; i < 4; ++i) {
            int idx = tid + i * 128;          // 0..511
            int r = idx >> 3, c16 = idx & 7;  // r < 64
            uint32_t soff = swz128((uint32_t)(r * 128 + c16 * 16));
            size_t go = gbase + (size_t)(c * 64 + r) * EMBED + c16 * 8;
            cpa16(tb +    0 + soff, Kh + go);
            cpa16(tb + 8192 + soff, Vh + go);
        }
        CP_COMMIT();
    };

    kvload(0, 0);
    CP_WAIT(0);
    __syncthreads();

    // Q fragments -> registers (persist): 2 m-blocks x 4 k-slices
    uint32_t qf[2][4][4];
#pragma unroll
    for (int mb = 0; mb < 2; ++mb)
#pragma unroll
        for (int ks = 0; ks < 4; ++ks) {
            uint32_t r  = wq + mb * 16 + (lane & 15);
            uint32_t ck = ks * 2 + (lane >> 4);
            uint32_t off = swz128(r * 128 + ck * 16);
            ldmx4(qf[mb][ks], ab + AQH + off);
        }

    const float CSC = 0.18033688011f;   // log2(e) / 8
    float lp[4] = {0.f, 0.f, 0.f, 0.f}; // per-thread row-sum partials
    float oac[2][8][4];
#pragma unroll
    for (int mb = 0; mb < 2; ++mb)
#pragma unroll
        for (int nt = 0; nt < 8; ++nt)
#pragma unroll
            for (int j = 0; j < 4; ++j) oac[mb][nt][j] = 0.f;

    const int NKV = SEQ / 64;   // 32
    for (int c = 0; c < NKV; ++c) {
        const int s = c & 1;
        const uint32_t tb = ab + AST + s * ASTG;
        if (c + 1 < NKV) kvload(c + 1, s ^ 1);

        // ---- S = Q K^T  (32 q-rows x 64 kv-cols per warp) ----
        float z[2][8][4];
#pragma unroll
        for (int mb = 0; mb < 2; ++mb)
#pragma unroll
            for (int nt = 0; nt < 8; ++nt)
#pragma unroll
                for (int j = 0; j < 4; ++j) z[mb][nt][j] = 0.f;

#pragma unroll
        for (int ks = 0; ks < 4; ++ks) {
            uint32_t k4[4][4];
#pragma unroll
            for (int np = 0; np < 4; ++np) {
                uint32_t r  = (np * 2 + (lane >> 4)) * 8 + (lane & 7);
                uint32_t ck = ks * 2 + ((lane >> 3) & 1);
                uint32_t off = swz128(r * 128 + ck * 16);
                ldmx4(k4[np], tb + off);
            }
#pragma unroll
            for (int mb = 0; mb < 2; ++mb)
#pragma unroll
                for (int nt = 0; nt < 8; ++nt)
                    mma16816(z[mb][nt], qf[mb][ks], &k4[nt >> 1][(nt & 1) * 2]);
        }

        // ---- elementwise exp + pack P to fp16; accumulate l partials ----
        uint32_t pp[2][16];
#pragma unroll
        for (int mb = 0; mb < 2; ++mb) {
            float s0 = 0.f, s1 = 0.f;
#pragma unroll
            for (int nt = 0; nt < 8; ++nt) {
                float e0 = ex2(z[mb][nt][0] * CSC);
                float e1 = ex2(z[mb][nt][1] * CSC);
                float e2 = ex2(z[mb][nt][2] * CSC);
                float e3 = ex2(z[mb][nt][3] * CSC);
                s0 += e0 + e1;
                s1 += e2 + e3;
                pp[mb][nt * 2]     = packf2(e0, e1);
                pp[mb][nt * 2 + 1] = packf2(e2, e3);
            }
            lp[2 * mb]     += s0;
            lp[2 * mb + 1] += s1;
        }

        // ---- O += P V  (V frags shared across m-blocks) ----
#pragma unroll
        for (int ksv = 0; ksv < 4; ++ksv) {
            uint32_t v4[4][4];
#pragma unroll
            for (int np = 0; np < 4; ++np) {
                uint32_t r  = ksv * 16 + ((lane >> 3) & 1) * 8 + (lane & 7);
                uint32_t ck = np * 2 + (lane >> 4);
                uint32_t off = swz128(r * 128 + ck * 16);
                ldmx4t(v4[np], tb + 8192 + off);
            }
#pragma unroll
            for (int mb = 0; mb < 2; ++mb) {
                const uint32_t* pa = &pp[mb][ksv * 4];
#pragma unroll
                for (int nt = 0; nt < 8; ++nt)
                    mma16816(oac[mb][nt], pa, &v4[nt >> 1][(nt & 1) * 2]);
            }
        }

        CP_WAIT(0);
        __syncthreads();
    }

    // ---- reduce l over the quad (cols spread across 4 lanes) ----
#pragma unroll
    for (int g = 0; g < 4; ++g) {
        lp[g] += __shfl_xor_sync(0xffffffffu, lp[g], 1);
        lp[g] += __shfl_xor_sync(0xffffffffu, lp[g], 2);
    }

    // ---- normalize + write Oh ----
#pragma unroll
    for (int mb = 0; mb < 2; ++mb) {
        float i0 = 1.0f / lp[2 * mb], i1 = 1.0f / lp[2 * mb + 1];
        int gr0 = q0 + wq + mb * 16 + (lane >> 2);
#pragma unroll
        for (int nt = 0; nt < 8; ++nt) {
            int cc = nt * 8 + (lane & 3) * 2;
            size_t o0 = gbase + (size_t)gr0 * EMBED + cc;
            size_t o1 = o0 + (size_t)8 * EMBED;
            *(uint32_t*)(Oh + o0) = packf2(oac[mb][nt][0] * i0,
                                           oac[mb][nt][1] * i0);
            *(uint32_t*)(Oh + o1) = packf2(oac[mb][nt][2] * i1,
                                           oac[mb][nt][3] * i1);
        }
    }
}

// ---------------------------------------------------------------------------
// Launch: 5 kernels.  attn_mma at launch index 3 (the ncu-profiled slot).
// ---------------------------------------------------------------------------
extern "C" void kernel_launch(void* const* d_in, const int* in_sizes, int n_in,
                              void* d_out, int out_size)
{
    const float* dec = (const float*)d_in[0];
    const float* enc = (const float*)d_in[1];
    const float* Wq  = (const float*)d_in[2];
    const float* Wk  = (const float*)d_in[3];
    const float* Wv  = (const float*)d_in[4];
    const float* Wo  = (const float*)d_in[5];
    const float* bo  = (const float*)d_in[6];
    float* out = (float*)d_out;

    h16 *dh, *eh, *qh, *kh, *vh, *oh, *wq, *wkv, *wo;
    cudaGetSymbolAddress((void**)&dh, g_dec_h);
    cudaGetSymbolAddress((void**)&eh, g_enc_h);
    cudaGetSymbolAddress((void**)&qh, g_qh);
    cudaGetSymbolAddress((void**)&kh, g_kh);
    cudaGetSymbolAddress((void**)&vh, g_vh);
    cudaGetSymbolAddress((void**)&oh, g_oh);
    cudaGetSymbolAddress((void**)&wq, g_wq);
    cudaGetSymbolAddress((void**)&wkv, g_wkv);
    cudaGetSymbolAddress((void**)&wo, g_wo);

    cudaFuncSetAttribute(gemm_qkv,
                         cudaFuncAttributeMaxDynamicSharedMemorySize, GSMEM);
    cudaFuncSetAttribute(gemm_o,
                         cudaFuncAttributeMaxDynamicSharedMemorySize, GSMEM);
    cudaFuncSetAttribute(attn_mma,
                         cudaFuncAttributeMaxDynamicSharedMemorySize, ASMEM);

    const int n8 = MTOT * EMBED / 8;   // 1,048,576

    // 0: all 4 weight transposes (wide stores, one launch)
    wtransx<<<dim3(EMBED / 32, EMBED / 64, 4), dim3(32, 8)>>>(
        Wq, Wk, Wv, Wo, wq, wkv, wo);
    // 1: dec + enc fp16 conversion
    tofp16_2<<<2 * n8 / 256, 256>>>(dec, enc, dh, eh, n8);
    // 2: fused Q+K+V projection
    gemm_qkv<<<dim3(24, MTOT / 128), 128, GSMEM>>>(dh, eh, wq, wkv,
                                                   qh, kh, vh);
    // 3: attention  (profiled slot)
    attn_mma<<<dim3(SEQ / 128, BATCH * HEADS), 128, ASMEM>>>(qh, kh, vh, oh);
    // 4: output projection + bias
    gemm_o<<<dim3(8, MTOT / 128), 128, GSMEM>>>(oh, wo, bo, out);
}